// round 16
// baseline (speedup 1.0000x reference)
#include <cuda_runtime.h>
#include <cuda_fp16.h>

#define D        32
#define NREL     16
#define NBASE    4
#define MAX_NODES 50176
#define NT       128          // nodes per phase-1 tile
#define NTHREADS 256

// Per-node src record: 160 halfs = 320 B : px[32] | z[128] (z chunk c: b0..b3 x4)
__device__ __half gSrc[MAX_NODES * 160];
__device__ __half gPyh[MAX_NODES * 32];
__device__ float  gAgg[MAX_NODES * D];          // init: curr = init_fea @ Wself
__device__ unsigned gBar;                        // monotonic grid barrier counter
__device__ unsigned gAck;                        // reset bookkeeping

// SMEM: sT[64*32]=2048 | sW[32*224]=7168 | sF[32*128]=4096  (two-pass staging)
#define K_SMEM_FLOATS (2048 + 7168 + 4096)
#define K_SMEM_BYTES  (K_SMEM_FLOATS * 4)       // 53,248 B -> 4 blocks/SM

// software grid barrier: safe because grid <= co-resident capacity (host-verified)
__device__ __forceinline__ void grid_barrier(unsigned target) {
    __threadfence();
    __syncthreads();
    if (threadIdx.x == 0) {
        atomicAdd(&gBar, 1u);
        while (atomicAdd(&gBar, 0u) < target) {
            __nanosleep(64);
        }
    }
    __syncthreads();
}

// ---------------------------------------------------------------------------
// Fused kernel: phase1 = node precompute (grid-strided tiles),
//               phase2 = edges, phase3 = relu -> out.
// ---------------------------------------------------------------------------
__global__ __launch_bounds__(NTHREADS)
void k_fused(const float* __restrict__ feat,
             const float* __restrict__ embed,
             const float* __restrict__ transform,
             const float* __restrict__ A_w,     // [96][32]; rows 0..63 = Ax,Ay
             const float* __restrict__ weight,  // [4][32][32]
             const float* __restrict__ wself,
             const float* __restrict__ A_b,
             const float* __restrict__ B_w,
             const float* __restrict__ B_b,
             const float* __restrict__ attn,
             const float* __restrict__ wcomp,
             const int* __restrict__ idx,
             const int* __restrict__ esrc, const int* __restrict__ edst,
             const int* __restrict__ etyp,
             float* __restrict__ out, int n, int nE, unsigned nGrid) {
    extern __shared__ float sm[];
    float* sT = sm;               // [64][32]
    float* sW = sm + 2048;        // [32][224]
    float* sF = sm + 9216;        // [32][128] staging (two passes); sI aliases
    float* sI = sF;

    int tid  = threadIdx.x;
    int w    = tid >> 5;
    int lane = tid & 31;
    int cg   = lane & 7;
    int ngl  = lane >> 3;
    int c0   = cg * 4;
    int n0   = w * 16 + ngl * 4;

    int nTiles = (n + NT - 1) / NT;       // 391

    // ================= PHASE 1: per-node precompute =================
    // stage weights once per block
    {
        const float4* Tv = (const float4*)transform;
        for (int i = tid; i < 512; i += 256) ((float4*)sT)[i] = __ldg(Tv + i);
        const float4* Av = (const float4*)A_w;
        for (int i = tid; i < 512; i += 256) {          // Ax,Ay
            int k = (i >> 3) & 31, part = i >> 8, c4 = i & 7;
            *(float4*)&sW[k * 224 + part * 32 + c4 * 4] = __ldg(Av + i);
        }
        const float4* Wv = (const float4*)weight;
        for (int i = tid; i < 1024; i += 256) {         // W0..W3
            int b = i >> 8, k = (i >> 3) & 31, c4 = i & 7;
            *(float4*)&sW[k * 224 + 64 + b * 32 + c4 * 4] = __ldg(Wv + i);
        }
        const float4* Sv = (const float4*)wself;
        for (int i = tid; i < 256; i += 256) {          // Wself
            int k = i >> 3, c4 = i & 7;
            *(float4*)&sW[k * 224 + 192 + c4 * 4] = __ldg(Sv + i);
        }
    }
    __syncthreads();

    int pS  = tid >> 7;
    int nlS = tid & 127;

    for (int tile = blockIdx.x; tile < nTiles; tile += nGrid) {
        int base = tile * NT;
        int nodeS = base + nlS;
        int ncS = nodeS < n ? nodeS : n - 1;
        int embRow = __ldg(idx + ncS);

        // --- stage pass A: feat rows ---
        {
            const float4* fr = (const float4*)feat + (size_t)ncS * 8 + pS * 4;
#pragma unroll
            for (int q = 0; q < 4; q++) {
                float4 v = __ldg(fr + q);
                int r = pS * 16 + q * 4;
                sF[(r + 0) * NT + nlS] = v.x; sF[(r + 1) * NT + nlS] = v.y;
                sF[(r + 2) * NT + nlS] = v.z; sF[(r + 3) * NT + nlS] = v.w;
            }
        }
        __syncthreads();

        float acc[4][4];
#pragma unroll
        for (int i = 0; i < 4; i++)
#pragma unroll
            for (int j = 0; j < 4; j++) acc[i][j] = 0.f;

#pragma unroll 8
        for (int k = 0; k < 32; k++) {
            float4 tv = *(const float4*)&sT[k * 32 + c0];
            float4 fv = *(const float4*)&sF[k * NT + n0];
            float f[4] = {fv.x, fv.y, fv.z, fv.w};
            float t[4] = {tv.x, tv.y, tv.z, tv.w};
#pragma unroll
            for (int i = 0; i < 4; i++)
#pragma unroll
                for (int j = 0; j < 4; j++)
                    acc[i][j] = fmaf(f[i], t[j], acc[i][j]);
        }
        __syncthreads();

        // --- stage pass B: embed rows ---
        {
            const float4* er = (const float4*)embed + (size_t)embRow * 8 + pS * 4;
#pragma unroll
            for (int q = 0; q < 4; q++) {
                float4 v = __ldg(er + q);
                int r = pS * 16 + q * 4;
                sF[(r + 0) * NT + nlS] = v.x; sF[(r + 1) * NT + nlS] = v.y;
                sF[(r + 2) * NT + nlS] = v.z; sF[(r + 3) * NT + nlS] = v.w;
            }
        }
        __syncthreads();

#pragma unroll 8
        for (int k = 0; k < 32; k++) {
            float4 tv = *(const float4*)&sT[(32 + k) * 32 + c0];
            float4 fv = *(const float4*)&sF[k * NT + n0];
            float f[4] = {fv.x, fv.y, fv.z, fv.w};
            float t[4] = {tv.x, tv.y, tv.z, tv.w};
#pragma unroll
            for (int i = 0; i < 4; i++)
#pragma unroll
                for (int j = 0; j < 4; j++)
                    acc[i][j] = fmaf(f[i], t[j], acc[i][j]);
        }
        __syncthreads();   // all sF reads done; sI may overwrite

        // epilogue: init_fea -> out[:,0,:], transposed copy -> sI
#pragma unroll
        for (int i = 0; i < 4; i++) {
            int node = base + n0 + i;
            if (node < n) {
                float4 v = make_float4(acc[i][0], acc[i][1], acc[i][2], acc[i][3]);
                *(float4*)&out[(size_t)node * 64 + c0] = v;
            }
#pragma unroll
            for (int j = 0; j < 4; j++)
                sI[(c0 + j) * NT + n0 + i] = acc[i][j];
        }
        __syncthreads();

        // --- GEMM2: 7 projections ---
#pragma unroll
        for (int pj = 0; pj < 7; pj++) {
            float a2[4][4];
#pragma unroll
            for (int i = 0; i < 4; i++)
#pragma unroll
                for (int j = 0; j < 4; j++) a2[i][j] = 0.f;
#pragma unroll 4
            for (int k = 0; k < 32; k++) {
                float4 nv = *(const float4*)&sI[k * NT + n0];
                float4 wv = *(const float4*)&sW[k * 224 + pj * 32 + c0];
                float f[4] = {nv.x, nv.y, nv.z, nv.w};
                float t[4] = {wv.x, wv.y, wv.z, wv.w};
#pragma unroll
                for (int i = 0; i < 4; i++)
#pragma unroll
                    for (int j = 0; j < 4; j++)
                        a2[i][j] = fmaf(f[i], t[j], a2[i][j]);
            }
#pragma unroll
            for (int i = 0; i < 4; i++) {
                int node = base + n0 + i;
                if (node >= n) continue;
                float4 v = make_float4(a2[i][0], a2[i][1], a2[i][2], a2[i][3]);
                __half2 h01 = __floats2half2_rn(v.x, v.y);
                __half2 h23 = __floats2half2_rn(v.z, v.w);
                uint2 pk;
                pk.x = *(unsigned*)&h01;
                pk.y = *(unsigned*)&h23;
                if (pj == 0) {
                    *(uint2*)&gSrc[(size_t)node * 160 + cg * 4] = pk;
                } else if (pj == 1) {
                    *(uint2*)&gPyh[(size_t)node * 32 + cg * 4] = pk;
                } else if (pj == 6) {
                    *(float4*)&gAgg[(size_t)node * D + c0] = v;
                } else {
                    int b = pj - 2;
                    *(uint2*)&gSrc[(size_t)node * 160 + 32 + cg * 16 + b * 4] = pk;
                }
            }
        }
        __syncthreads();   // sI reads done before next tile restages sF
    }

    // ================= BARRIER 1 =================
    grid_barrier(nGrid);

    // ================= PHASE 2: edges =================
    {
        float* sPr = sm;            // [512] reuse sT region
        float* sWc = sm + 512;      // [64]
        for (int i = tid; i < NREL * D; i += 256) {
            int t = i >> 5, o = i & 31;
            float acc = __ldg(A_b + o);
#pragma unroll
            for (int k = 0; k < D; k++)
                acc = fmaf(__ldg(attn + t * D + k), __ldg(A_w + (64 + k) * D + o), acc);
            sPr[i] = acc;
        }
        if (tid < NREL * NBASE) sWc[tid] = wcomp[tid];
        __syncthreads();

        int ei = lane >> 3;
        float Bb = __ldg(B_b);
        float4 Bw4 = __ldg((const float4*)B_w + cg);

        int gwarp = blockIdx.x * 8 + w;
        int nWarps = nGrid * 8;
        int nQ = (nE + 3) >> 2;

        const uint2* Pxv = (const uint2*)gSrc;
        const uint4* Zv  = (const uint4*)gSrc;
        const uint2* Pyv = (const uint2*)gPyh;
        const float4* Prv = (const float4*)sPr;
        const float4* Wcv = (const float4*)sWc;

        for (int q = gwarp; q < nQ; q += nWarps) {
            int ge = q * 4 + ei;
            bool valid = ge < nE;
            int gc = valid ? ge : (nE - 1);
            int src = __ldg(esrc + gc);
            int dst = __ldg(edst + gc);
            int typ = __ldg(etyp + gc);

            uint2 pxu = __ldg(Pxv + (size_t)src * 40 + cg);
            uint2 pyu = __ldg(Pyv + (size_t)dst * 8 + cg);
            uint4 u0  = __ldg(Zv + (size_t)src * 20 + 4 + cg * 2);
            uint4 u1  = __ldg(Zv + (size_t)src * 20 + 5 + cg * 2);
            float4 pr4 = Prv[typ * 8 + cg];

            float2 px01 = __half22float2(*(const __half2*)&pxu.x);
            float2 px23 = __half22float2(*(const __half2*)&pxu.y);
            float2 py01 = __half22float2(*(const __half2*)&pyu.x);
            float2 py23 = __half22float2(*(const __half2*)&pyu.y);

            float hx = fmaxf(px01.x + py01.x + pr4.x, 0.f);
            float hy = fmaxf(px01.y + py01.y + pr4.y, 0.f);
            float hz = fmaxf(px23.x + py23.x + pr4.z, 0.f);
            float hw = fmaxf(px23.y + py23.y + pr4.w, 0.f);
            float s = hx * Bw4.x + hy * Bw4.y + hz * Bw4.z + hw * Bw4.w;
            s += __shfl_xor_sync(0xffffffffu, s, 1);
            s += __shfl_xor_sync(0xffffffffu, s, 2);
            s += __shfl_xor_sync(0xffffffffu, s, 4);
            float a = 1.f / (1.f + __expf(-(s + Bb)));

            float2 f00 = __half22float2(*(const __half2*)&u0.x);
            float2 f01 = __half22float2(*(const __half2*)&u0.y);
            float2 f10 = __half22float2(*(const __half2*)&u0.z);
            float2 f11 = __half22float2(*(const __half2*)&u0.w);
            float2 f20 = __half22float2(*(const __half2*)&u1.x);
            float2 f21 = __half22float2(*(const __half2*)&u1.y);
            float2 f30 = __half22float2(*(const __half2*)&u1.z);
            float2 f31 = __half22float2(*(const __half2*)&u1.w);

            float4 wc = Wcv[typ];
            float mx = wc.x * f00.x; mx = fmaf(wc.y, f10.x, mx); mx = fmaf(wc.z, f20.x, mx); mx = fmaf(wc.w, f30.x, mx);
            float my = wc.x * f00.y; my = fmaf(wc.y, f10.y, my); my = fmaf(wc.z, f20.y, my); my = fmaf(wc.w, f30.y, my);
            float mz = wc.x * f01.x; mz = fmaf(wc.y, f11.x, mz); mz = fmaf(wc.z, f21.x, mz); mz = fmaf(wc.w, f31.x, mz);
            float mw = wc.x * f01.y; mw = fmaf(wc.y, f11.y, mw); mw = fmaf(wc.z, f21.y, mw); mw = fmaf(wc.w, f31.y, mw);
            mx *= a; my *= a; mz *= a; mw *= a;

            if (valid) {
                float* p = &gAgg[(size_t)dst * D + cg * 4];
                asm volatile("red.global.add.v4.f32 [%0], {%1,%2,%3,%4};"
                             :: "l"(p), "f"(mx), "f"(my), "f"(mz), "f"(mw)
                             : "memory");
            }
        }
    }

    // ================= BARRIER 2 =================
    grid_barrier(2u * nGrid);

    // ================= PHASE 3: relu -> out =================
    {
        int total = n * 8;
        int stride = nGrid * NTHREADS;
        for (int i = blockIdx.x * NTHREADS + tid; i < total; i += stride) {
            int v = i >> 3, cc = i & 7;
            float4 g = *(const float4*)&gAgg[(size_t)i * 4];
            float4 r;
            r.x = fmaxf(g.x, 0.f); r.y = fmaxf(g.y, 0.f);
            r.z = fmaxf(g.z, 0.f); r.w = fmaxf(g.w, 0.f);
            ((float4*)out)[(size_t)v * 16 + 8 + cc] = r;
        }
    }

    // ---- reset barrier counters for next graph replay ----
    // Safe: every block increments gAck only AFTER passing barrier 2's spin,
    // so when the last block resets, no spinner can still be reading gBar.
    if (tid == 0) {
        unsigned prev = atomicAdd(&gAck, 1u);
        if (prev == nGrid - 1) {
            gBar = 0u;
            gAck = 0u;
            __threadfence();
        }
    }
}

// ---------------------------------------------------------------------------
extern "C" void kernel_launch(void* const* d_in, const int* in_sizes, int n_in,
                              void* d_out, int out_size) {
    const float* feat      = (const float*)d_in[0];
    const float* embed     = (const float*)d_in[1];
    const float* transform = (const float*)d_in[2];
    const float* weight    = (const float*)d_in[3];
    const float* wcomp     = (const float*)d_in[4];
    const float* wself     = (const float*)d_in[5];
    const float* A_w       = (const float*)d_in[6];
    const float* A_b       = (const float*)d_in[7];
    const float* B_w       = (const float*)d_in[8];
    const float* B_b       = (const float*)d_in[9];
    const float* attn      = (const float*)d_in[10];
    const int*   idx       = (const int*)d_in[11];
    const int*   esrc      = (const int*)d_in[12];
    const int*   edst      = (const int*)d_in[13];
    const int*   etyp      = (const int*)d_in[14];

    int n  = in_sizes[0] / D;       // 50000
    int nE = in_sizes[12];          // 800000
    float* out = (float*)d_out;

    cudaFuncSetAttribute(k_fused, cudaFuncAttributeMaxDynamicSharedMemorySize, K_SMEM_BYTES);

    // host-verified co-resident grid (deterministic query APIs, capture-legal)
    int dev = 0, sms = 0, perSM = 0;
    cudaGetDevice(&dev);
    cudaDeviceGetAttribute(&sms, cudaDevAttrMultiProcessorCount, dev);
    cudaOccupancyMaxActiveBlocksPerMultiprocessor(&perSM, k_fused, NTHREADS, K_SMEM_BYTES);
    if (perSM < 1) perSM = 1;
    unsigned nGrid = (unsigned)(perSM * sms);

    k_fused<<<nGrid, NTHREADS, K_SMEM_BYTES>>>(feat, embed, transform, A_w, weight,
                                               wself, A_b, B_w, B_b, attn, wcomp,
                                               idx, esrc, edst, etyp, out, n, nE, nGrid);
}

// round 17
// speedup vs baseline: 1.1648x; 1.1648x over previous
#include <cuda_runtime.h>
#include <cuda_fp16.h>

#define D        32
#define NREL     16
#define NBASE    4
#define MAX_NODES 50176
#define NT       128          // nodes per k1 block

// Per-node src record: 160 halfs = 320 B : px[32] | z[128] (z chunk c: b0..b3 x4)
__device__ __half gSrc[MAX_NODES * 160];
__device__ __half gPyh[MAX_NODES * 32];
__device__ float  gAgg[MAX_NODES * D];          // init: curr = init_fea @ Wself

// k1 SMEM: sT[64*32]=2048 | sW[32*224]=7168 | sF[32*128]=4096 (two passes; sI aliases)
#define K1_SMEM_FLOATS (2048 + 7168 + 4096)
#define K1_SMEM_BYTES  (K1_SMEM_FLOATS * 4)

// ---------------------------------------------------------------------------
// K1: per-node precompute, tiled GEMM form.
//   GEMM1: init = [feat | embed[idx]] @ transform   (two 32-k passes)
//   GEMM2: init @ [Ax | Ay | W0..W3 | Wself]        (128x32 @ 32x224)
// ---------------------------------------------------------------------------
__global__ __launch_bounds__(256)
void k1_init(const float* __restrict__ feat,
             const float* __restrict__ embed,
             const float* __restrict__ transform,
             const float* __restrict__ A_w,     // [96][32]; rows 0..63 = Ax,Ay
             const float* __restrict__ weight,  // [4][32][32]
             const float* __restrict__ wself,
             const int* __restrict__ idx,
             float* __restrict__ out, int n) {
    extern __shared__ float sm[];
    float* sT = sm;              // [64][32]
    float* sW = sm + 2048;       // [32][224]
    float* sF = sm + 9216;       // [32][128]
    float* sI = sF;

    int tid = threadIdx.x;
    {
        const float4* Tv = (const float4*)transform;
        for (int i = tid; i < 512; i += 256) ((float4*)sT)[i] = __ldg(Tv + i);
        const float4* Av = (const float4*)A_w;
        for (int i = tid; i < 512; i += 256) {          // Ax,Ay
            int k = (i >> 3) & 31, part = i >> 8, c4 = i & 7;
            *(float4*)&sW[k * 224 + part * 32 + c4 * 4] = __ldg(Av + i);
        }
        const float4* Wv = (const float4*)weight;
        for (int i = tid; i < 1024; i += 256) {         // W0..W3
            int b = i >> 8, k = (i >> 3) & 31, c4 = i & 7;
            *(float4*)&sW[k * 224 + 64 + b * 32 + c4 * 4] = __ldg(Wv + i);
        }
        const float4* Sv = (const float4*)wself;
        for (int i = tid; i < 256; i += 256) {          // Wself
            int k = i >> 3, c4 = i & 7;
            *(float4*)&sW[k * 224 + 192 + c4 * 4] = __ldg(Sv + i);
        }
    }

    int base = blockIdx.x * NT;
    int pS  = tid >> 7;
    int nlS = tid & 127;
    int nodeS = base + nlS;
    int ncS = nodeS < n ? nodeS : n - 1;
    int embRow = __ldg(idx + ncS);

    // --- stage pass A: feat rows ---
    {
        const float4* fr = (const float4*)feat + (size_t)ncS * 8 + pS * 4;
#pragma unroll
        for (int q = 0; q < 4; q++) {
            float4 v = __ldg(fr + q);
            int r = pS * 16 + q * 4;
            sF[(r + 0) * NT + nlS] = v.x; sF[(r + 1) * NT + nlS] = v.y;
            sF[(r + 2) * NT + nlS] = v.z; sF[(r + 3) * NT + nlS] = v.w;
        }
    }
    __syncthreads();

    int w    = tid >> 5;
    int lane = tid & 31;
    int cg  = lane & 7;
    int ngl = lane >> 3;
    int n0  = w * 16 + ngl * 4;
    int c0  = cg * 4;

    float acc[4][4];
#pragma unroll
    for (int i = 0; i < 4; i++)
#pragma unroll
        for (int j = 0; j < 4; j++) acc[i][j] = 0.f;

#pragma unroll 8
    for (int k = 0; k < 32; k++) {
        float4 tv = *(const float4*)&sT[k * 32 + c0];
        float4 fv = *(const float4*)&sF[k * NT + n0];
        float f[4] = {fv.x, fv.y, fv.z, fv.w};
        float t[4] = {tv.x, tv.y, tv.z, tv.w};
#pragma unroll
        for (int i = 0; i < 4; i++)
#pragma unroll
            for (int j = 0; j < 4; j++)
                acc[i][j] = fmaf(f[i], t[j], acc[i][j]);
    }
    __syncthreads();

    // --- stage pass B: embed rows ---
    {
        const float4* er = (const float4*)embed + (size_t)embRow * 8 + pS * 4;
#pragma unroll
        for (int q = 0; q < 4; q++) {
            float4 v = __ldg(er + q);
            int r = pS * 16 + q * 4;
            sF[(r + 0) * NT + nlS] = v.x; sF[(r + 1) * NT + nlS] = v.y;
            sF[(r + 2) * NT + nlS] = v.z; sF[(r + 3) * NT + nlS] = v.w;
        }
    }
    __syncthreads();

#pragma unroll 8
    for (int k = 0; k < 32; k++) {
        float4 tv = *(const float4*)&sT[(32 + k) * 32 + c0];
        float4 fv = *(const float4*)&sF[k * NT + n0];
        float f[4] = {fv.x, fv.y, fv.z, fv.w};
        float t[4] = {tv.x, tv.y, tv.z, tv.w};
#pragma unroll
        for (int i = 0; i < 4; i++)
#pragma unroll
            for (int j = 0; j < 4; j++)
                acc[i][j] = fmaf(f[i], t[j], acc[i][j]);
    }
    __syncthreads();

    // epilogue: write init_fea to out[:,0,:] and transposed copy into sI
#pragma unroll
    for (int i = 0; i < 4; i++) {
        int node = base + n0 + i;
        if (node < n) {
            float4 v = make_float4(acc[i][0], acc[i][1], acc[i][2], acc[i][3]);
            *(float4*)&out[(size_t)node * 64 + c0] = v;
        }
#pragma unroll
        for (int j = 0; j < 4; j++)
            sI[(c0 + j) * NT + n0 + i] = acc[i][j];
    }
    __syncthreads();

    // --- GEMM2: 7 projections ---
#pragma unroll
    for (int pj = 0; pj < 7; pj++) {
        float a2[4][4];
#pragma unroll
        for (int i = 0; i < 4; i++)
#pragma unroll
            for (int j = 0; j < 4; j++) a2[i][j] = 0.f;
#pragma unroll 4
        for (int k = 0; k < 32; k++) {
            float4 nv = *(const float4*)&sI[k * NT + n0];
            float4 wv = *(const float4*)&sW[k * 224 + pj * 32 + c0];
            float f[4] = {nv.x, nv.y, nv.z, nv.w};
            float t[4] = {wv.x, wv.y, wv.z, wv.w};
#pragma unroll
            for (int i = 0; i < 4; i++)
#pragma unroll
                for (int j = 0; j < 4; j++)
                    a2[i][j] = fmaf(f[i], t[j], a2[i][j]);
        }
#pragma unroll
        for (int i = 0; i < 4; i++) {
            int node = base + n0 + i;
            if (node >= n) continue;
            float4 v = make_float4(a2[i][0], a2[i][1], a2[i][2], a2[i][3]);
            __half2 h01 = __floats2half2_rn(v.x, v.y);
            __half2 h23 = __floats2half2_rn(v.z, v.w);
            uint2 pk;
            pk.x = *(unsigned*)&h01;
            pk.y = *(unsigned*)&h23;
            if (pj == 0) {            // px fp16 -> gSrc[0..32)
                *(uint2*)&gSrc[(size_t)node * 160 + cg * 4] = pk;
            } else if (pj == 1) {     // py fp16
                *(uint2*)&gPyh[(size_t)node * 32 + cg * 4] = pk;
            } else if (pj == 6) {     // curr fp32
                *(float4*)&gAgg[(size_t)node * D + c0] = v;
            } else {                  // z_b fp16 -> gSrc[32 + c*16 + b*4]
                int b = pj - 2;
                *(uint2*)&gSrc[(size_t)node * 160 + 32 + cg * 16 + b * 4] = pk;
            }
        }
    }
}

// ---------------------------------------------------------------------------
// K2: edge kernel. 4 edges/warp, 8 lanes/edge (lane c = float4 chunk).
// ---------------------------------------------------------------------------
__global__ __launch_bounds__(256)
void k2_edges(const float* __restrict__ A_w, const float* __restrict__ A_b,
              const float* __restrict__ B_w, const float* __restrict__ B_b,
              const float* __restrict__ attn, const float* __restrict__ wcomp,
              const int* __restrict__ esrc, const int* __restrict__ edst,
              const int* __restrict__ etyp, int nE) {
    __shared__ float sPr[NREL * D];
    __shared__ float sWc[NREL * NBASE];
    int tid = threadIdx.x;
    for (int i = tid; i < NREL * D; i += 256) {
        int t = i >> 5, o = i & 31;
        float acc = __ldg(A_b + o);
#pragma unroll
        for (int k = 0; k < D; k++)
            acc = fmaf(__ldg(attn + t * D + k), __ldg(A_w + (64 + k) * D + o), acc);
        sPr[i] = acc;
    }
    if (tid < NREL * NBASE) sWc[tid] = wcomp[tid];
    __syncthreads();

    int lane = tid & 31;
    int c    = lane & 7;
    int ei   = lane >> 3;
    float Bb = __ldg(B_b);
    float4 Bw4 = __ldg((const float4*)B_w + c);

    int gwarp = (blockIdx.x * blockDim.x + tid) >> 5;
    int nWarps = (gridDim.x * blockDim.x) >> 5;
    int nQ = (nE + 3) >> 2;

    const uint2* Pxv = (const uint2*)gSrc;   // 40 uint2 per node
    const uint4* Zv  = (const uint4*)gSrc;   // 20 uint4 per node; z at +4
    const uint2* Pyv = (const uint2*)gPyh;   // 8 uint2 per node
    const float4* Prv = (const float4*)sPr;
    const float4* Wcv = (const float4*)sWc;

    for (int q = gwarp; q < nQ; q += nWarps) {
        int ge = q * 4 + ei;
        bool valid = ge < nE;
        int gc = valid ? ge : (nE - 1);
        int src = __ldg(esrc + gc);
        int dst = __ldg(edst + gc);
        int typ = __ldg(etyp + gc);

        uint2 pxu = __ldg(Pxv + (size_t)src * 40 + c);
        uint2 pyu = __ldg(Pyv + (size_t)dst * 8 + c);
        uint4 u0  = __ldg(Zv + (size_t)src * 20 + 4 + c * 2);      // b0,b1
        uint4 u1  = __ldg(Zv + (size_t)src * 20 + 5 + c * 2);      // b2,b3
        float4 pr4 = Prv[typ * 8 + c];

        float2 px01 = __half22float2(*(const __half2*)&pxu.x);
        float2 px23 = __half22float2(*(const __half2*)&pxu.y);
        float2 py01 = __half22float2(*(const __half2*)&pyu.x);
        float2 py23 = __half22float2(*(const __half2*)&pyu.y);

        float hx = fmaxf(px01.x + py01.x + pr4.x, 0.f);
        float hy = fmaxf(px01.y + py01.y + pr4.y, 0.f);
        float hz = fmaxf(px23.x + py23.x + pr4.z, 0.f);
        float hw = fmaxf(px23.y + py23.y + pr4.w, 0.f);
        float s = hx * Bw4.x + hy * Bw4.y + hz * Bw4.z + hw * Bw4.w;
        s += __shfl_xor_sync(0xffffffffu, s, 1);
        s += __shfl_xor_sync(0xffffffffu, s, 2);
        s += __shfl_xor_sync(0xffffffffu, s, 4);
        float a = 1.f / (1.f + __expf(-(s + Bb)));

        float2 f00 = __half22float2(*(const __half2*)&u0.x);
        float2 f01 = __half22float2(*(const __half2*)&u0.y);
        float2 f10 = __half22float2(*(const __half2*)&u0.z);
        float2 f11 = __half22float2(*(const __half2*)&u0.w);
        float2 f20 = __half22float2(*(const __half2*)&u1.x);
        float2 f21 = __half22float2(*(const __half2*)&u1.y);
        float2 f30 = __half22float2(*(const __half2*)&u1.z);
        float2 f31 = __half22float2(*(const __half2*)&u1.w);

        float4 wc = Wcv[typ];
        float mx = wc.x * f00.x; mx = fmaf(wc.y, f10.x, mx); mx = fmaf(wc.z, f20.x, mx); mx = fmaf(wc.w, f30.x, mx);
        float my = wc.x * f00.y; my = fmaf(wc.y, f10.y, my); my = fmaf(wc.z, f20.y, my); my = fmaf(wc.w, f30.y, my);
        float mz = wc.x * f01.x; mz = fmaf(wc.y, f11.x, mz); mz = fmaf(wc.z, f21.x, mz); mz = fmaf(wc.w, f31.x, mz);
        float mw = wc.x * f01.y; mw = fmaf(wc.y, f11.y, mw); mw = fmaf(wc.z, f21.y, mw); mw = fmaf(wc.w, f31.y, mw);
        mx *= a; my *= a; mz *= a; mw *= a;

        if (valid) {
            float* p = &gAgg[(size_t)dst * D + c * 4];
            asm volatile("red.global.add.v4.f32 [%0], {%1,%2,%3,%4};"
                         :: "l"(p), "f"(mx), "f"(my), "f"(mz), "f"(mw)
                         : "memory");
        }
    }
}

// ---------------------------------------------------------------------------
// K3: repr[:,1,:] = relu(gAgg), 4 float4 per thread
// ---------------------------------------------------------------------------
__global__ void k3_final(float* __restrict__ out, int n) {
    int total = n * 8;
    int stride = gridDim.x * blockDim.x;
    int i0 = blockIdx.x * blockDim.x + threadIdx.x;
#pragma unroll 4
    for (int it = 0; it < 4; it++) {
        int i = i0 + it * stride;
        if (i < total) {
            int v = i >> 3, cc = i & 7;
            float4 g = ((const float4*)gAgg)[i];
            float4 r;
            r.x = fmaxf(g.x, 0.f); r.y = fmaxf(g.y, 0.f);
            r.z = fmaxf(g.z, 0.f); r.w = fmaxf(g.w, 0.f);
            ((float4*)out)[(size_t)v * 16 + 8 + cc] = r;
        }
    }
}

// ---------------------------------------------------------------------------
extern "C" void kernel_launch(void* const* d_in, const int* in_sizes, int n_in,
                              void* d_out, int out_size) {
    const float* feat      = (const float*)d_in[0];
    const float* embed     = (const float*)d_in[1];
    const float* transform = (const float*)d_in[2];
    const float* weight    = (const float*)d_in[3];
    const float* wcomp     = (const float*)d_in[4];
    const float* wself     = (const float*)d_in[5];
    const float* A_w       = (const float*)d_in[6];
    const float* A_b       = (const float*)d_in[7];
    const float* B_w       = (const float*)d_in[8];
    const float* B_b       = (const float*)d_in[9];
    const float* attn      = (const float*)d_in[10];
    const int*   idx       = (const int*)d_in[11];
    const int*   esrc      = (const int*)d_in[12];
    const int*   edst      = (const int*)d_in[13];
    const int*   etyp      = (const int*)d_in[14];

    int n  = in_sizes[0] / D;       // 50000
    int nE = in_sizes[12];          // 800000
    float* out = (float*)d_out;

    cudaFuncSetAttribute(k1_init, cudaFuncAttributeMaxDynamicSharedMemorySize, K1_SMEM_BYTES);

    k1_init<<<(n + NT - 1) / NT, 256, K1_SMEM_BYTES>>>(feat, embed, transform, A_w,
                                                       weight, wself, idx, out, n);
    k2_edges<<<1184, 256>>>(A_w, A_b, B_w, B_b, attn, wcomp, esrc, edst, etyp, nE);
    k3_final<<<(n * 8 + 4 * 256 - 1) / (4 * 256), 256>>>(out, n);
}